// round 1
// baseline (speedup 1.0000x reference)
#include <cuda_runtime.h>
#include <math.h>

#define BATCH 4
#define SEQL  2048
#define DIM   768
#define NST   16
#define BL    (BATCH*SEQL)

#define TL 64
#define KC 32

// scratch (static device globals — no runtime allocation)
__device__ float g_delta[BL];
__device__ float g_Bt[NST*BL];
__device__ float g_Ct[NST*BL];

__device__ __forceinline__ float ex2f(float x) {
    float y;
    asm("ex2.approx.ftz.f32 %0, %1;" : "=f"(y) : "f"(x));
    return y;
}

// ---------------- kernel 1a: delta[b*l] = softplus(p_delta + u . q_delta) ----
__global__ void delta_kernel(const float* __restrict__ u,
                             const float* __restrict__ q_delta,
                             const float* __restrict__ p_delta) {
    int warp = (blockIdx.x * blockDim.x + threadIdx.x) >> 5;
    int lane = threadIdx.x & 31;
    if (warp >= BL) return;
    const float* up = u + (size_t)warp * DIM;
    float s = 0.f;
#pragma unroll
    for (int j = 0; j < 6; j++) {
        float4 uv = *(const float4*)(up      + j*128 + lane*4);
        float4 qv = *(const float4*)(q_delta + j*128 + lane*4);
        s = fmaf(uv.x, qv.x, s);
        s = fmaf(uv.y, qv.y, s);
        s = fmaf(uv.z, qv.z, s);
        s = fmaf(uv.w, qv.w, s);
    }
#pragma unroll
    for (int o = 16; o; o >>= 1) s += __shfl_xor_sync(0xffffffffu, s, o);
    if (lane == 0) {
        float z = s + p_delta[0];
        g_delta[warp] = (z > 20.f) ? z : log1pf(__expf(z));
    }
}

// ---------------- kernel 1b: Bt[n][bl], Ct[n][bl] = W_B/W_C @ u^T ------------
// out[32][8192] = W[32][768] * u^T[768][8192], tiled: TL=64 positions/block.
__global__ void proj_kernel(const float* __restrict__ u,
                            const float* __restrict__ W_B,
                            const float* __restrict__ W_C) {
    __shared__ __align__(16) float Us[KC*68];  // [k][pos], pad 68 for bank/align
    __shared__ __align__(16) float Ws[KC*36];  // [k][j],  pad 36 (16B aligned rows)
    int t  = threadIdx.x;       // 128 threads
    int tx = t & 15;            // pos group (4 pos)
    int ty = t >> 4;            // j group  (4 j), 0..7
    int blb = blockIdx.x * TL;  // position base

    float acc[4][4];
#pragma unroll
    for (int a = 0; a < 4; a++)
#pragma unroll
        for (int c = 0; c < 4; c++) acc[a][c] = 0.f;

    for (int dc = 0; dc < DIM; dc += KC) {
        // stage u tile [TL][KC] transposed into Us[k][pos] (coalesced gmem reads)
#pragma unroll
        for (int it = 0; it < (TL*KC)/128; it++) {
            int idx = t + it*128;
            int k = idx & 31, p = idx >> 5;
            Us[k*68 + p] = u[(size_t)(blb + p)*DIM + dc + k];
        }
        // stage W tile [32][KC] transposed into Ws[k][j]
#pragma unroll
        for (int it = 0; it < (32*KC)/128; it++) {
            int idx = t + it*128;
            int k = idx & 31, j = idx >> 5;
            const float* wr = (j < 16) ? (W_B + j*DIM) : (W_C + (j-16)*DIM);
            Ws[k*36 + j] = wr[dc + k];
        }
        __syncthreads();
#pragma unroll
        for (int k = 0; k < KC; k++) {
            float4 u4 = *(const float4*)(Us + k*68 + tx*4);
            float4 w4 = *(const float4*)(Ws + k*36 + ty*4);
            float us[4] = {u4.x, u4.y, u4.z, u4.w};
            float ws[4] = {w4.x, w4.y, w4.z, w4.w};
#pragma unroll
            for (int a = 0; a < 4; a++)
#pragma unroll
                for (int c = 0; c < 4; c++)
                    acc[a][c] = fmaf(ws[a], us[c], acc[a][c]);
        }
        __syncthreads();
    }
#pragma unroll
    for (int a = 0; a < 4; a++) {
        int j = ty*4 + a;
        float* dst = (j < 16) ? (g_Bt + j*BL) : (g_Ct + (j-16)*BL);
        float4 v = make_float4(acc[a][0], acc[a][1], acc[a][2], acc[a][3]);
        *(float4*)(dst + blb + tx*4) = v;
    }
}

// ---------------- kernel 2: selective scan -----------------------------------
// lane = n (16 lanes per (b,d) group, 2 groups per warp); x in register;
// per-timestep n-reduction via 4-level shfl.xor butterfly.
__global__ void scan_kernel(const float* __restrict__ u,
                            const float* __restrict__ A,
                            float* __restrict__ y) {
    int tid = blockIdx.x * blockDim.x + threadIdx.x;
    int g = tid >> 4;       // (b,d) group
    int n = tid & 15;
    int b = g / DIM;
    int d = g - b * DIM;

    float a2 = A[d*NST + n] * 1.4426950408889634f;  // fold log2(e)
    const float* dp = g_delta + b*SEQL;
    const float* Bp = g_Bt + n*BL + b*SEQL;
    const float* Cp = g_Ct + n*BL + b*SEQL;
    const float* up = u + (size_t)b*SEQL*DIM + d;
    float*       yp = y + (size_t)b*SEQL*DIM + d;

    float x = 0.f;
    for (int l = 0; l < SEQL; l += 4) {
        float4 d4 = *(const float4*)(dp + l);
        float4 b4 = *(const float4*)(Bp + l);
        float4 c4 = *(const float4*)(Cp + l);
        float dls[4] = {d4.x, d4.y, d4.z, d4.w};
        float bs[4]  = {b4.x, b4.y, b4.z, b4.w};
        float cs[4]  = {c4.x, c4.y, c4.z, c4.w};
#pragma unroll
        for (int j = 0; j < 4; j++) {
            float ul = up[(size_t)(l+j)*DIM];
            float dA = ex2f(dls[j] * a2);
            x = fmaf(dA, x, dls[j] * ul * bs[j]);
            float p = x * cs[j];
            p += __shfl_xor_sync(0xffffffffu, p, 1);
            p += __shfl_xor_sync(0xffffffffu, p, 2);
            p += __shfl_xor_sync(0xffffffffu, p, 4);
            p += __shfl_xor_sync(0xffffffffu, p, 8);
            if (n == 0) yp[(size_t)(l+j)*DIM] = p;
        }
    }
}

extern "C" void kernel_launch(void* const* d_in, const int* in_sizes, int n_in,
                              void* d_out, int out_size) {
    const float* u       = (const float*)d_in[0];
    const float* A       = (const float*)d_in[1];
    const float* W_B     = (const float*)d_in[2];
    const float* W_C     = (const float*)d_in[3];
    const float* q_delta = (const float*)d_in[4];
    const float* p_delta = (const float*)d_in[5];
    float* y = (float*)d_out;

    delta_kernel<<<BL/8, 256>>>(u, q_delta, p_delta);
    proj_kernel<<<BL/TL, 128>>>(u, W_B, W_C);
    scan_kernel<<<(BATCH*DIM*NST)/64, 64>>>(u, A, y);
}